// round 9
// baseline (speedup 1.0000x reference)
#include <cuda_runtime.h>
#include <cstdint>

// SceneContraction: TMA-staged 2-subtile pipeline (R8) + L2 residency policy:
// input loads L2::evict_last (retained across graph replays; input re-read
// every replay), output stores L2::evict_first (dead lines don't displace
// resident input). Targets DRAM *traffic*, the only remaining lever --
// schedule variants R5-R8 all plateau at ~6.2 TB/s.
// means = contract(mean); cov_out = J cov J (J symmetric) for ||x||>=1 else pass.
// J = g*I + c*x x^T, g=(2-1/m)/m, c=2(1-m)/m^4, m=||x||.

#define TPB         256
#define SUB         256                   // samples per subtile (1/thread)
#define SPB         (2 * SUB)             // 512 samples per CTA
#define MEAN_F      (SUB * 3)             // 768 floats
#define COV_F       (SUB * 9)             // 2304 floats
#define MEAN_B      (MEAN_F * 4)          // 3072 bytes
#define COV_B       (COV_F * 4)           // 9216 bytes
#define SUB_BYTES   (MEAN_B + COV_B)      // 12288 bytes

__device__ __forceinline__ uint32_t smem_u32(const void* p) {
    return (uint32_t)__cvta_generic_to_shared(p);
}

__device__ __forceinline__ void mbar_wait0(uint32_t mbar) {
    uint32_t done;
    asm volatile(
        "{\n\t.reg .pred p;\n\t"
        "mbarrier.try_wait.parity.shared.b64 p, [%1], 0;\n\t"
        "selp.b32 %0, 1, 0, p;\n\t}"
        : "=r"(done) : "r"(mbar) : "memory");
    if (!done) {
        asm volatile(
            "{\n\t.reg .pred P1;\n"
            "WL_%=:\n\t"
            "mbarrier.try_wait.parity.shared.b64 P1, [%0], 0;\n\t"
            "@P1 bra.uni WD_%=;\n\t"
            "bra.uni WL_%=;\n"
            "WD_%=:\n\t}"
            :: "r"(mbar) : "memory");
    }
}

__device__ __forceinline__ void contract_one(
    float x0, float x1, float x2,
    float c00, float c01, float c02,
    float c10, float c11, float c12,
    float c20, float c21, float c22,
    float& r0, float& r1, float& r2,
    float& o00, float& o01, float& o02,
    float& o10, float& o11, float& o12,
    float& o20, float& o21, float& o22)
{
    float m2 = fmaf(x0, x0, fmaf(x1, x1, x2 * x2));
    float m  = sqrtf(m2);

    r0 = x0; r1 = x1; r2 = x2;
    o00 = c00; o01 = c01; o02 = c02;
    o10 = c10; o11 = c11; o12 = c12;
    o20 = c20; o21 = c21; o22 = c22;

    if (m >= 1.0f) {
        float inv  = 1.0f / m;
        float g    = (2.0f - inv) * inv;
        float inv2 = inv * inv;
        float cc   = 2.0f * (1.0f - m) * inv2 * inv2;

        r0 = g * x0; r1 = g * x1; r2 = g * x2;

        float J00 = fmaf(cc, x0 * x0, g);
        float J11 = fmaf(cc, x1 * x1, g);
        float J22 = fmaf(cc, x2 * x2, g);
        float J01 = cc * x0 * x1;
        float J02 = cc * x0 * x2;
        float J12 = cc * x1 * x2;

        float b00 = J00*c00 + J01*c10 + J02*c20;
        float b01 = J00*c01 + J01*c11 + J02*c21;
        float b02 = J00*c02 + J01*c12 + J02*c22;
        float b10 = J01*c00 + J11*c10 + J12*c20;
        float b11 = J01*c01 + J11*c11 + J12*c21;
        float b12 = J01*c02 + J11*c12 + J12*c22;
        float b20 = J02*c00 + J12*c10 + J22*c20;
        float b21 = J02*c01 + J12*c11 + J22*c21;
        float b22 = J02*c02 + J12*c12 + J22*c22;

        o00 = b00*J00 + b01*J01 + b02*J02;
        o01 = b00*J01 + b01*J11 + b02*J12;
        o02 = b00*J02 + b01*J12 + b02*J22;
        o10 = b10*J00 + b11*J01 + b12*J02;
        o11 = b10*J01 + b11*J11 + b12*J12;
        o12 = b10*J02 + b11*J12 + b12*J22;
        o20 = b20*J00 + b21*J01 + b22*J02;
        o21 = b20*J01 + b21*J11 + b22*J12;
        o22 = b20*J02 + b21*J12 + b22*J22;
    }
}

struct SubBuf { float mean[MEAN_F]; float cov[COV_F]; };

__global__ __launch_bounds__(TPB) void scene_contraction_kernel(
    const float* __restrict__ mean,   // [N,3]
    const float* __restrict__ cov,    // [N,3,3]
    float* __restrict__ out_mean,     // [N,3]
    float* __restrict__ out_cov,      // [N,3,3]
    int n)
{
    __shared__ alignas(128) SubBuf sbuf[2];
    __shared__ alignas(8) unsigned long long s_mbar[2];

    const int t = threadIdx.x;
    const int base = blockIdx.x * SPB;

    if (base + SPB <= n) {
        const uint32_t mb0 = smem_u32(&s_mbar[0]);
        const uint32_t mb1 = smem_u32(&s_mbar[1]);

        if (t == 0) {
            asm volatile("mbarrier.init.shared.b64 [%0], 1;" :: "r"(mb0) : "memory");
            asm volatile("mbarrier.init.shared.b64 [%0], 1;" :: "r"(mb1) : "memory");
        }
        __syncthreads();

        // issue BOTH subtile loads upfront, input marked L2::evict_last
        if (t == 0) {
            uint64_t pol_ld;
            asm("createpolicy.fractional.L2::evict_last.b64 %0, 1.0;" : "=l"(pol_ld));
            #pragma unroll
            for (int s = 0; s < 2; s++) {
                const uint32_t mb = s ? mb1 : mb0;
                const uint32_t smn = smem_u32(sbuf[s].mean);
                const uint32_t scv = smem_u32(sbuf[s].cov);
                const size_t sub = (size_t)(blockIdx.x * 2 + s);
                const float* gm = mean + sub * MEAN_F;
                const float* gc = cov  + sub * COV_F;
                asm volatile("mbarrier.arrive.expect_tx.shared.b64 _, [%0], %1;"
                             :: "r"(mb), "r"((uint32_t)SUB_BYTES) : "memory");
                asm volatile("cp.async.bulk.shared::cta.global.mbarrier::complete_tx::bytes.L2::cache_hint "
                             "[%0], [%1], %2, [%3], %4;"
                             :: "r"(scv), "l"(gc), "r"((uint32_t)COV_B), "r"(mb), "l"(pol_ld) : "memory");
                asm volatile("cp.async.bulk.shared::cta.global.mbarrier::complete_tx::bytes.L2::cache_hint "
                             "[%0], [%1], %2, [%3], %4;"
                             :: "r"(smn), "l"(gm), "r"((uint32_t)MEAN_B), "r"(mb), "l"(pol_ld) : "memory");
            }
        }

        #pragma unroll
        for (int s = 0; s < 2; s++) {
            float* smn = sbuf[s].mean;
            float* scv = sbuf[s].cov;

            mbar_wait0(s ? mb1 : mb0);

            // 1 sample/thread, results in place (each thread's region disjoint)
            const int idx = t;
            float x0 = smn[3*idx+0], x1 = smn[3*idx+1], x2 = smn[3*idx+2];
            float c00 = scv[9*idx+0], c01 = scv[9*idx+1], c02 = scv[9*idx+2];
            float c10 = scv[9*idx+3], c11 = scv[9*idx+4], c12 = scv[9*idx+5];
            float c20 = scv[9*idx+6], c21 = scv[9*idx+7], c22 = scv[9*idx+8];

            float r0, r1, r2, o00, o01, o02, o10, o11, o12, o20, o21, o22;
            contract_one(x0, x1, x2, c00, c01, c02, c10, c11, c12, c20, c21, c22,
                         r0, r1, r2, o00, o01, o02, o10, o11, o12, o20, o21, o22);

            smn[3*idx+0] = r0;  smn[3*idx+1] = r1;  smn[3*idx+2] = r2;
            scv[9*idx+0] = o00; scv[9*idx+1] = o01; scv[9*idx+2] = o02;
            scv[9*idx+3] = o10; scv[9*idx+4] = o11; scv[9*idx+5] = o12;
            scv[9*idx+6] = o20; scv[9*idx+7] = o21; scv[9*idx+8] = o22;

            __syncthreads();

            // async store of this subtile (L2::evict_first); overlaps next compute
            if (t == 0) {
                uint64_t pol_st;
                asm("createpolicy.fractional.L2::evict_first.b64 %0, 1.0;" : "=l"(pol_st));
                asm volatile("fence.proxy.async.shared::cta;" ::: "memory");
                const size_t sub = (size_t)(blockIdx.x * 2 + s);
                float* om = out_mean + sub * MEAN_F;
                float* oc = out_cov  + sub * COV_F;
                asm volatile("cp.async.bulk.global.shared::cta.bulk_group.L2::cache_hint "
                             "[%0], [%1], %2, %3;"
                             :: "l"(oc), "r"(smem_u32(scv)), "r"((uint32_t)COV_B), "l"(pol_st) : "memory");
                asm volatile("cp.async.bulk.global.shared::cta.bulk_group.L2::cache_hint "
                             "[%0], [%1], %2, %3;"
                             :: "l"(om), "r"(smem_u32(smn)), "r"((uint32_t)MEAN_B), "l"(pol_st) : "memory");
                asm volatile("cp.async.bulk.commit_group;" ::: "memory");
            }
        }

        // drain outstanding stores before CTA exit (smem lifetime safety)
        if (t == 0) {
            asm volatile("cp.async.bulk.wait_group 0;" ::: "memory");
        }
    } else {
        // ---- scalar tail path ----
        for (int s = 0; s < 2; s++) {
            int i = base + t + s * TPB;
            if (i >= n) return;
            const float* xp = mean + 3ull * i;
            const float* cp = cov + 9ull * i;
            float r0, r1, r2, o00, o01, o02, o10, o11, o12, o20, o21, o22;
            contract_one(xp[0], xp[1], xp[2],
                         cp[0], cp[1], cp[2], cp[3], cp[4], cp[5], cp[6], cp[7], cp[8],
                         r0, r1, r2, o00, o01, o02, o10, o11, o12, o20, o21, o22);
            float* om = out_mean + 3ull * i;
            float* oc = out_cov  + 9ull * i;
            om[0]=r0; om[1]=r1; om[2]=r2;
            oc[0]=o00; oc[1]=o01; oc[2]=o02;
            oc[3]=o10; oc[4]=o11; oc[5]=o12;
            oc[6]=o20; oc[7]=o21; oc[8]=o22;
        }
    }
}

extern "C" void kernel_launch(void* const* d_in, const int* in_sizes, int n_in,
                              void* d_out, int out_size)
{
    const float* mean = (const float*)d_in[0];   // [N,3]
    const float* cov  = (const float*)d_in[1];   // [N,3,3]
    int n = in_sizes[0] / 3;

    float* out_mean = (float*)d_out;
    float* out_cov  = (float*)d_out + 3ull * n;

    int blocks = (n + SPB - 1) / SPB;
    scene_contraction_kernel<<<blocks, TPB>>>(mean, cov, out_mean, out_cov, n);
}

// round 10
// speedup vs baseline: 1.0157x; 1.0157x over previous
#include <cuda_runtime.h>
#include <cstdint>

// SceneContraction hybrid: TMA bulk LOAD into smem + coalesced STG.128 STORES.
// (TMA loads gave best ncu kernel time; STG stores belonged to the best
// wall-clock kernel. Testing the store-side hypothesis for the steady-state
// inversion.) SPB=256, TPB=256, compute in place, 2 barriers.
// means = contract(mean); cov_out = J cov J (J symmetric) for ||x||>=1 else pass.
// J = g*I + c*x x^T, g=(2-1/m)/m, c=2(1-m)/m^4, m=||x||.

#define TPB         256
#define SPB         256
#define MEAN_F      (SPB * 3)            // 768 floats
#define COV_F       (SPB * 9)            // 2304 floats
#define MEAN_B      (MEAN_F * 4)         // 3072 bytes
#define COV_B       (COV_F * 4)          // 9216 bytes
#define TILE_BYTES  (MEAN_B + COV_B)
#define M4          (MEAN_F / 4)         // 192 float4
#define C4          (COV_F / 4)          // 576 float4

__device__ __forceinline__ uint32_t smem_u32(const void* p) {
    return (uint32_t)__cvta_generic_to_shared(p);
}

__device__ __forceinline__ void contract_one(
    float x0, float x1, float x2,
    float c00, float c01, float c02,
    float c10, float c11, float c12,
    float c20, float c21, float c22,
    float& r0, float& r1, float& r2,
    float& o00, float& o01, float& o02,
    float& o10, float& o11, float& o12,
    float& o20, float& o21, float& o22)
{
    float m2 = fmaf(x0, x0, fmaf(x1, x1, x2 * x2));
    float m  = sqrtf(m2);

    r0 = x0; r1 = x1; r2 = x2;
    o00 = c00; o01 = c01; o02 = c02;
    o10 = c10; o11 = c11; o12 = c12;
    o20 = c20; o21 = c21; o22 = c22;

    if (m >= 1.0f) {
        float inv  = 1.0f / m;
        float g    = (2.0f - inv) * inv;
        float inv2 = inv * inv;
        float cc   = 2.0f * (1.0f - m) * inv2 * inv2;

        r0 = g * x0; r1 = g * x1; r2 = g * x2;

        float J00 = fmaf(cc, x0 * x0, g);
        float J11 = fmaf(cc, x1 * x1, g);
        float J22 = fmaf(cc, x2 * x2, g);
        float J01 = cc * x0 * x1;
        float J02 = cc * x0 * x2;
        float J12 = cc * x1 * x2;

        float b00 = J00*c00 + J01*c10 + J02*c20;
        float b01 = J00*c01 + J01*c11 + J02*c21;
        float b02 = J00*c02 + J01*c12 + J02*c22;
        float b10 = J01*c00 + J11*c10 + J12*c20;
        float b11 = J01*c01 + J11*c11 + J12*c21;
        float b12 = J01*c02 + J11*c12 + J12*c22;
        float b20 = J02*c00 + J12*c10 + J22*c20;
        float b21 = J02*c01 + J12*c11 + J22*c21;
        float b22 = J02*c02 + J12*c12 + J22*c22;

        o00 = b00*J00 + b01*J01 + b02*J02;
        o01 = b00*J01 + b01*J11 + b02*J12;
        o02 = b00*J02 + b01*J12 + b02*J22;
        o10 = b10*J00 + b11*J01 + b12*J02;
        o11 = b10*J01 + b11*J11 + b12*J12;
        o12 = b10*J02 + b11*J12 + b12*J22;
        o20 = b20*J00 + b21*J01 + b22*J02;
        o21 = b20*J01 + b21*J11 + b22*J12;
        o22 = b20*J02 + b21*J12 + b22*J22;
    }
}

__global__ __launch_bounds__(TPB) void scene_contraction_kernel(
    const float* __restrict__ mean,   // [N,3]
    const float* __restrict__ cov,    // [N,3,3]
    float* __restrict__ out_mean,     // [N,3]
    float* __restrict__ out_cov,      // [N,3,3]
    int n)
{
    __shared__ alignas(128) float s_mean[MEAN_F];
    __shared__ alignas(128) float s_cov[COV_F];
    __shared__ alignas(8) unsigned long long s_mbar;

    const int t = threadIdx.x;
    const int base = blockIdx.x * SPB;

    if (base + SPB <= n) {
        const uint32_t mbar = smem_u32(&s_mbar);
        const uint32_t smn  = smem_u32(s_mean);
        const uint32_t scv  = smem_u32(s_cov);

        if (t == 0) {
            asm volatile("mbarrier.init.shared.b64 [%0], 1;" :: "r"(mbar) : "memory");
        }
        __syncthreads();

        if (t == 0) {
            const float* gm = mean + (size_t)blockIdx.x * MEAN_F;
            const float* gc = cov  + (size_t)blockIdx.x * COV_F;
            asm volatile("mbarrier.arrive.expect_tx.shared.b64 _, [%0], %1;"
                         :: "r"(mbar), "r"((uint32_t)TILE_BYTES) : "memory");
            asm volatile("cp.async.bulk.shared::cta.global.mbarrier::complete_tx::bytes "
                         "[%0], [%1], %2, [%3];"
                         :: "r"(scv), "l"(gc), "r"((uint32_t)COV_B), "r"(mbar) : "memory");
            asm volatile("cp.async.bulk.shared::cta.global.mbarrier::complete_tx::bytes "
                         "[%0], [%1], %2, [%3];"
                         :: "r"(smn), "l"(gm), "r"((uint32_t)MEAN_B), "r"(mbar) : "memory");
        }

        // all threads wait on the tile (phase 0)
        {
            uint32_t done;
            asm volatile(
                "{\n\t.reg .pred p;\n\t"
                "mbarrier.try_wait.parity.shared.b64 p, [%1], 0;\n\t"
                "selp.b32 %0, 1, 0, p;\n\t}"
                : "=r"(done) : "r"(mbar) : "memory");
            if (!done) {
                asm volatile(
                    "{\n\t.reg .pred P1;\n"
                    "WL_%=:\n\t"
                    "mbarrier.try_wait.parity.shared.b64 P1, [%0], 0;\n\t"
                    "@P1 bra.uni WD_%=;\n\t"
                    "bra.uni WL_%=;\n"
                    "WD_%=:\n\t}"
                    :: "r"(mbar) : "memory");
            }
        }

        // ---- compute 1 sample/thread, results in place (disjoint regions) ----
        {
            float x0 = s_mean[3*t+0], x1 = s_mean[3*t+1], x2 = s_mean[3*t+2];
            float c00 = s_cov[9*t+0], c01 = s_cov[9*t+1], c02 = s_cov[9*t+2];
            float c10 = s_cov[9*t+3], c11 = s_cov[9*t+4], c12 = s_cov[9*t+5];
            float c20 = s_cov[9*t+6], c21 = s_cov[9*t+7], c22 = s_cov[9*t+8];

            float r0, r1, r2, o00, o01, o02, o10, o11, o12, o20, o21, o22;
            contract_one(x0, x1, x2, c00, c01, c02, c10, c11, c12, c20, c21, c22,
                         r0, r1, r2, o00, o01, o02, o10, o11, o12, o20, o21, o22);

            s_mean[3*t+0] = r0;  s_mean[3*t+1] = r1;  s_mean[3*t+2] = r2;
            s_cov[9*t+0] = o00;  s_cov[9*t+1] = o01;  s_cov[9*t+2] = o02;
            s_cov[9*t+3] = o10;  s_cov[9*t+4] = o11;  s_cov[9*t+5] = o12;
            s_cov[9*t+6] = o20;  s_cov[9*t+7] = o21;  s_cov[9*t+8] = o22;
        }
        __syncthreads();

        // ---- coalesced STG.128 stores from smem ----
        const float4* sm4 = reinterpret_cast<const float4*>(s_mean);
        const float4* sc4 = reinterpret_cast<const float4*>(s_cov);
        float4* om = reinterpret_cast<float4*>(out_mean) + (size_t)blockIdx.x * M4;
        float4* oc = reinterpret_cast<float4*>(out_cov)  + (size_t)blockIdx.x * C4;
        if (t < M4) om[t] = sm4[t];
        #pragma unroll
        for (int i = t; i < C4; i += TPB) oc[i] = sc4[i];
    } else {
        // ---- scalar tail path ----
        int i = base + t;
        if (i >= n) return;
        const float* xp = mean + 3ull * i;
        const float* cp = cov + 9ull * i;
        float r0, r1, r2, o00, o01, o02, o10, o11, o12, o20, o21, o22;
        contract_one(xp[0], xp[1], xp[2],
                     cp[0], cp[1], cp[2], cp[3], cp[4], cp[5], cp[6], cp[7], cp[8],
                     r0, r1, r2, o00, o01, o02, o10, o11, o12, o20, o21, o22);
        float* om = out_mean + 3ull * i;
        float* oc = out_cov  + 9ull * i;
        om[0]=r0; om[1]=r1; om[2]=r2;
        oc[0]=o00; oc[1]=o01; oc[2]=o02;
        oc[3]=o10; oc[4]=o11; oc[5]=o12;
        oc[6]=o20; oc[7]=o21; oc[8]=o22;
    }
}

extern "C" void kernel_launch(void* const* d_in, const int* in_sizes, int n_in,
                              void* d_out, int out_size)
{
    const float* mean = (const float*)d_in[0];   // [N,3]
    const float* cov  = (const float*)d_in[1];   // [N,3,3]
    int n = in_sizes[0] / 3;

    float* out_mean = (float*)d_out;
    float* out_cov  = (float*)d_out + 3ull * n;

    int blocks = (n + SPB - 1) / SPB;
    scene_contraction_kernel<<<blocks, TPB>>>(mean, cov, out_mean, out_cov, n);
}